// round 2
// baseline (speedup 1.0000x reference)
#include <cuda_runtime.h>
#include <math.h>

#define NN   8192
#define DIN  256
#define DOUT 128
#define TI   32      // rows per block in main kernel
#define CJ   64      // j-chunk
#define WSTR 36      // padded stride for w tile (floats), 16B-aligned rows

// ---- scratch (no allocs allowed) ----
__device__ float g_h[NN * DOUT];     // 4MB, fits L2
__device__ float g_ssrc[NN];
__device__ float g_sdst[NN];
__device__ float g_p[NN];
__device__ float g_q[NN];
__device__ float g_A[NN];
__device__ float g_B[NN];
__device__ float g_V;

// =====================================================================
// k1: h = x @ W + bW ; also per-row s_src = h.a1, s_dst = h.a2
// block: 128 threads, tile 32 rows x 128 cols, K=256 in chunks of 16
// =====================================================================
__global__ void __launch_bounds__(128) k_linear(
    const float* __restrict__ x, const float* __restrict__ W,
    const float* __restrict__ bW, const float* __restrict__ a1,
    const float* __restrict__ a2)
{
    __shared__ __align__(16) float xs[16][33];     // [k][row], padded
    __shared__ __align__(16) float Ws[16][DOUT];   // [k][col]

    const int tid = threadIdx.x;
    const int dg = tid & 15;        // col group: cols [8*dg, 8*dg+8)
    const int rg = tid >> 4;        // row group: rows [4*rg, 4*rg+4)
    const int row0 = blockIdx.x * TI;

    float acc[4][8];
#pragma unroll
    for (int r = 0; r < 4; r++)
#pragma unroll
        for (int c = 0; c < 8; c++) acc[r][c] = 0.f;

    for (int kb = 0; kb < DIN; kb += 16) {
        __syncthreads();
        // x tile (transposed into [k][row])
#pragma unroll
        for (int m = 0; m < 4; m++) {
            int i = tid + 128 * m;
            int rr = i >> 4, kk = i & 15;
            xs[kk][rr] = x[(row0 + rr) * DIN + kb + kk];
        }
        // W tile (contiguous copy)
        const float4* Wg = (const float4*)(W + kb * DOUT);
        float4* Wl = (float4*)Ws;
#pragma unroll
        for (int m = 0; m < 4; m++) Wl[tid + 128 * m] = Wg[tid + 128 * m];
        __syncthreads();

#pragma unroll
        for (int k = 0; k < 16; k++) {
            float a_[4];
#pragma unroll
            for (int r = 0; r < 4; r++) a_[r] = xs[k][rg * 4 + r];
            float4 b0 = *(const float4*)&Ws[k][dg * 8];
            float4 b1 = *(const float4*)&Ws[k][dg * 8 + 4];
            float b_[8] = {b0.x, b0.y, b0.z, b0.w, b1.x, b1.y, b1.z, b1.w};
#pragma unroll
            for (int r = 0; r < 4; r++)
#pragma unroll
                for (int c = 0; c < 8; c++) acc[r][c] = fmaf(a_[r], b_[c], acc[r][c]);
        }
    }

    // epilogue: bias, store h, per-row dot with a1/a2
    float4 bv0 = *(const float4*)&bW[dg * 8];
    float4 bv1 = *(const float4*)&bW[dg * 8 + 4];
    float bv[8] = {bv0.x, bv0.y, bv0.z, bv0.w, bv1.x, bv1.y, bv1.z, bv1.w};
    float4 a10 = *(const float4*)&a1[dg * 8];
    float4 a11 = *(const float4*)&a1[dg * 8 + 4];
    float a1v[8] = {a10.x, a10.y, a10.z, a10.w, a11.x, a11.y, a11.z, a11.w};
    float4 a20 = *(const float4*)&a2[dg * 8];
    float4 a21 = *(const float4*)&a2[dg * 8 + 4];
    float a2v[8] = {a20.x, a20.y, a20.z, a20.w, a21.x, a21.y, a21.z, a21.w};

    float s1[4], s2[4];
#pragma unroll
    for (int r = 0; r < 4; r++) {
        s1[r] = 0.f; s2[r] = 0.f;
#pragma unroll
        for (int c = 0; c < 8; c++) {
            acc[r][c] += bv[c];
            s1[r] = fmaf(acc[r][c], a1v[c], s1[r]);
            s2[r] = fmaf(acc[r][c], a2v[c], s2[r]);
        }
        int row = row0 + rg * 4 + r;
        float4 o0 = make_float4(acc[r][0], acc[r][1], acc[r][2], acc[r][3]);
        float4 o1 = make_float4(acc[r][4], acc[r][5], acc[r][6], acc[r][7]);
        *(float4*)&g_h[row * DOUT + dg * 8]     = o0;
        *(float4*)&g_h[row * DOUT + dg * 8 + 4] = o1;
    }
    // reduce s over the 16 dg lanes
#pragma unroll
    for (int r = 0; r < 4; r++) {
#pragma unroll
        for (int off = 8; off > 0; off >>= 1) {
            s1[r] += __shfl_down_sync(0xffffffffu, s1[r], off, 16);
            s2[r] += __shfl_down_sync(0xffffffffu, s2[r], off, 16);
        }
    }
    if (dg == 0) {
#pragma unroll
        for (int r = 0; r < 4; r++) {
            int row = row0 + rg * 4 + r;
            g_ssrc[row] = s1[r];
            g_sdst[row] = s2[r];
        }
    }
}

// =====================================================================
// k2a: p = exp(s_dst), q = exp(0.01*s_dst), V = max(s_dst). 1 block.
// =====================================================================
__global__ void __launch_bounds__(1024) k_prep1()
{
    __shared__ float red[32];
    int tid = threadIdx.x;
    int lane = tid & 31, wid = tid >> 5;
    float vmax = -1e30f;
    for (int j = tid; j < NN; j += 1024) {
        float v = g_sdst[j];
        g_p[j] = expf(v);
        g_q[j] = expf(0.01f * v);
        vmax = fmaxf(vmax, v);
    }
#pragma unroll
    for (int off = 16; off > 0; off >>= 1)
        vmax = fmaxf(vmax, __shfl_down_sync(0xffffffffu, vmax, off));
    if (lane == 0) red[wid] = vmax;
    __syncthreads();
    if (wid == 0) {
        float m = red[lane];
#pragma unroll
        for (int off = 16; off > 0; off >>= 1)
            m = fmaxf(m, __shfl_down_sync(0xffffffffu, m, off));
        if (lane == 0) g_V = m;
    }
}

// =====================================================================
// k2b: per-row A_i, B_i with shift c_i = lrelu(u_i + V)
// =====================================================================
__global__ void k_prep2(const float* __restrict__ ba)
{
    int i = blockIdx.x * blockDim.x + threadIdx.x;
    if (i >= NN) return;
    float u = g_ssrc[i] + ba[0];
    float t0 = u + g_V;
    float c = fmaxf(t0, 0.01f * t0);     // lrelu(t0), valid for both signs
    g_A[i] = expf(u - c);
    g_B[i] = expf(0.01f * u - c);
}

// =====================================================================
// k3: out[i,:] = (sum_j w_ij * h_j) / (sum_j w_ij)
//     w_ij = adj_ij ? max(A_i*p_j, B_i*q_j) : 0
// block: 128 threads; 32 rows x 128 dims; packed f32x2 FFMA main loop
// =====================================================================
#define FMA2(acc_, a_, b_) asm("fma.rn.f32x2 %0, %1, %2, %0;" \
    : "+l"(acc_) : "l"(a_), "l"(b_))

__global__ void __launch_bounds__(128) k_main(
    const int* __restrict__ adj, float* __restrict__ out)
{
    __shared__ __align__(16) float2 h2s[CJ][DOUT / 2];   // 32KB
    __shared__ __align__(16) float  ws[CJ][WSTR];        // 9KB, [j][row]
    __shared__ float denom_s[TI];

    const int tid = threadIdx.x;
    const int dg = tid & 15;      // dim-pair group: dpairs [4*dg, 4*dg+4)
    const int rg = tid >> 4;      // row group: rows [4*rg, 4*rg+4)
    const int row0 = blockIdx.x * TI;

    // generation mapping: one j column, 16 rows per thread
    const int jl = tid & 63;
    const int rh = tid >> 6;      // 0/1 -> rows [16*rh, 16*rh+16)

    float Ar[16], Br[16];
#pragma unroll
    for (int k = 0; k < 16; k++) {
        Ar[k] = g_A[row0 + rh * 16 + k];
        Br[k] = g_B[row0 + rh * 16 + k];
    }

    unsigned long long acc[16];
#pragma unroll
    for (int i = 0; i < 16; i++) acc[i] = 0ULL;
    float dsum[4] = {0.f, 0.f, 0.f, 0.f};

    for (int jb = 0; jb < NN; jb += CJ) {
        __syncthreads();
        // ---- load h chunk: CJ x 128 floats ----
        {
            const float4* hg = (const float4*)(g_h + jb * DOUT);
            float4* hl = (float4*)h2s;
#pragma unroll
            for (int m = 0; m < 16; m++) hl[tid + 128 * m] = hg[tid + 128 * m];
        }
        // ---- generate w tile ----
        {
            float pj = g_p[jb + jl];
            float qj = g_q[jb + jl];
            const int* arow = adj + (row0 + rh * 16) * NN + jb + jl;
            int av[16];
#pragma unroll
            for (int k = 0; k < 16; k++) av[k] = arow[k * NN];   // 16 in-flight loads
#pragma unroll
            for (int m = 0; m < 4; m++) {
                float4 wbuf;
                float* wp = (float*)&wbuf;
#pragma unroll
                for (int k = 0; k < 4; k++) {
                    int kk = m * 4 + k;
                    float w = fmaxf(Ar[kk] * pj, Br[kk] * qj);
                    wp[k] = av[kk] ? w : 0.f;
                }
                *(float4*)&ws[jl][rh * 16 + m * 4] = wbuf;
            }
        }
        __syncthreads();
        // ---- accumulate: 16 f32x2 FMA per j per thread ----
#pragma unroll 4
        for (int j = 0; j < CJ; j++) {
            float4 w4 = *(const float4*)&ws[j][rg * 4];
            ulonglong2 hA = *(const ulonglong2*)&h2s[j][dg * 4];
            ulonglong2 hB = *(const ulonglong2*)&h2s[j][dg * 4 + 2];
            unsigned long long w2[4];
            asm("mov.b64 %0, {%1,%1};" : "=l"(w2[0]) : "f"(w4.x));
            asm("mov.b64 %0, {%1,%1};" : "=l"(w2[1]) : "f"(w4.y));
            asm("mov.b64 %0, {%1,%1};" : "=l"(w2[2]) : "f"(w4.z));
            asm("mov.b64 %0, {%1,%1};" : "=l"(w2[3]) : "f"(w4.w));
#pragma unroll
            for (int r = 0; r < 4; r++) {
                FMA2(acc[r * 4 + 0], w2[r], hA.x);
                FMA2(acc[r * 4 + 1], w2[r], hA.y);
                FMA2(acc[r * 4 + 2], w2[r], hB.x);
                FMA2(acc[r * 4 + 3], w2[r], hB.y);
            }
            if (dg == 0) {      // denominator: dg==0 lanes see every (row,j) w
                dsum[0] += w4.x; dsum[1] += w4.y;
                dsum[2] += w4.z; dsum[3] += w4.w;
            }
        }
    }

    if (dg == 0) {
#pragma unroll
        for (int r = 0; r < 4; r++) denom_s[rg * 4 + r] = dsum[r];
    }
    __syncthreads();

#pragma unroll
    for (int r = 0; r < 4; r++) {
        float inv = 1.0f / fmaxf(denom_s[rg * 4 + r], 1e-30f);
        int ob = (row0 + rg * 4 + r) * DOUT + dg * 8;
#pragma unroll
        for (int dp = 0; dp < 4; dp++) {
            float2 v = *(float2*)&acc[r * 4 + dp];
            v.x *= inv; v.y *= inv;
            *(float2*)&out[ob + 2 * dp] = v;
        }
    }
}

// =====================================================================
extern "C" void kernel_launch(void* const* d_in, const int* in_sizes, int n_in,
                              void* d_out, int out_size)
{
    const float* x   = (const float*)d_in[0];
    const int*   adj = (const int*)  d_in[1];
    const float* W   = (const float*)d_in[2];
    const float* bW  = (const float*)d_in[3];
    const float* a1  = (const float*)d_in[4];
    const float* a2  = (const float*)d_in[5];
    const float* ba  = (const float*)d_in[6];
    float* out = (float*)d_out;

    k_linear<<<NN / TI, 128>>>(x, W, bW, a1, a2);
    k_prep1<<<1, 1024>>>();
    k_prep2<<<NN / 256, 256>>>(ba);
    k_main<<<NN / TI, 128>>>(adj, out);
}

// round 4
// speedup vs baseline: 4.4065x; 4.4065x over previous
#include <cuda_runtime.h>
#include <cuda_fp16.h>
#include <math.h>
#include <stdint.h>

#define NN   8192
#define DIN  256
#define DOUT 128
#define TI   32
#define JS   4              // j segments
#define SEG  (NN / JS)      // 2048
#define KC   64             // j per chunk
#define NCH  (SEG / KC)     // 32

// ---- scratch ----
__device__ float  g_ssrc[NN];
__device__ float  g_sdst[NN];
__device__ float  g_p[NN];
__device__ float  g_q[NN];
__device__ float  g_A[NN];
__device__ float  g_B[NN];
__device__ float  g_V;
__device__ __half g_hT[(size_t)DOUT * NN];            // h transposed, fp16 (2MB)
__device__ float  g_part[(size_t)JS * NN * DOUT];     // 16MB partial numerators
__device__ float  g_denomp[JS * NN];

// ============================ PTX helpers ============================
__device__ __forceinline__ uint32_t smem_u32(const void* p) {
    uint32_t a;
    asm("{ .reg .u64 t; cvta.to.shared.u64 t, %1; cvt.u32.u64 %0, t; }" : "=r"(a) : "l"(p));
    return a;
}
#define LDMX4(r0, r1, r2, r3, a) \
    asm volatile("ldmatrix.sync.aligned.m8n8.x4.shared.b16 {%0,%1,%2,%3}, [%4];" \
                 : "=r"(r0), "=r"(r1), "=r"(r2), "=r"(r3) : "r"(a))
#define MMA16816(c, a0, a1, a2, a3, b0, b1) \
    asm volatile("mma.sync.aligned.m16n8k16.row.col.f32.f16.f16.f32 " \
                 "{%0,%1,%2,%3},{%4,%5,%6,%7},{%8,%9},{%0,%1,%2,%3};" \
                 : "+f"((c)[0]), "+f"((c)[1]), "+f"((c)[2]), "+f"((c)[3]) \
                 : "r"(a0), "r"(a1), "r"(a2), "r"(a3), "r"(b0), "r"(b1))
#define CPASYNC16(dst, src) \
    asm volatile("cp.async.ca.shared.global [%0], [%1], 16;" :: "r"(dst), "l"(src))
#define CPCOMMIT() asm volatile("cp.async.commit_group;" ::: "memory")
#define CPWAIT0()  asm volatile("cp.async.wait_group 0;" ::: "memory")

// =====================================================================
// k1: h = x@W + bW (fp32), store hT fp16; s_src = h.a1, s_dst = h.a2
// =====================================================================
__global__ void __launch_bounds__(128) k_linear(
    const float* __restrict__ x, const float* __restrict__ W,
    const float* __restrict__ bW, const float* __restrict__ a1,
    const float* __restrict__ a2)
{
    __shared__ __align__(16) float xs[16][33];
    __shared__ __align__(16) float Ws[16][DOUT];

    const int tid = threadIdx.x;
    const int dg = tid & 15;
    const int rg = tid >> 4;
    const int row0 = blockIdx.x * TI;

    float acc[4][8];
#pragma unroll
    for (int r = 0; r < 4; r++)
#pragma unroll
        for (int c = 0; c < 8; c++) acc[r][c] = 0.f;

    for (int kb = 0; kb < DIN; kb += 16) {
        __syncthreads();
#pragma unroll
        for (int m = 0; m < 4; m++) {
            int i = tid + 128 * m;
            int rr = i >> 4, kk = i & 15;
            xs[kk][rr] = x[(row0 + rr) * DIN + kb + kk];
        }
        const float4* Wg = (const float4*)(W + kb * DOUT);
        float4* Wl = (float4*)Ws;
#pragma unroll
        for (int m = 0; m < 4; m++) Wl[tid + 128 * m] = Wg[tid + 128 * m];
        __syncthreads();

#pragma unroll
        for (int k = 0; k < 16; k++) {
            float a_[4];
#pragma unroll
            for (int r = 0; r < 4; r++) a_[r] = xs[k][rg * 4 + r];
            float4 b0 = *(const float4*)&Ws[k][dg * 8];
            float4 b1 = *(const float4*)&Ws[k][dg * 8 + 4];
            float b_[8] = {b0.x, b0.y, b0.z, b0.w, b1.x, b1.y, b1.z, b1.w};
#pragma unroll
            for (int r = 0; r < 4; r++)
#pragma unroll
                for (int c = 0; c < 8; c++) acc[r][c] = fmaf(a_[r], b_[c], acc[r][c]);
        }
    }

    float4 bv0 = *(const float4*)&bW[dg * 8];
    float4 bv1 = *(const float4*)&bW[dg * 8 + 4];
    float bv[8] = {bv0.x, bv0.y, bv0.z, bv0.w, bv1.x, bv1.y, bv1.z, bv1.w};
    float4 a10 = *(const float4*)&a1[dg * 8];
    float4 a11 = *(const float4*)&a1[dg * 8 + 4];
    float a1v[8] = {a10.x, a10.y, a10.z, a10.w, a11.x, a11.y, a11.z, a11.w};
    float4 a20 = *(const float4*)&a2[dg * 8];
    float4 a21 = *(const float4*)&a2[dg * 8 + 4];
    float a2v[8] = {a20.x, a20.y, a20.z, a20.w, a21.x, a21.y, a21.z, a21.w};

    float s1[4], s2[4];
#pragma unroll
    for (int r = 0; r < 4; r++) {
        s1[r] = 0.f; s2[r] = 0.f;
        int row = row0 + rg * 4 + r;
#pragma unroll
        for (int c = 0; c < 8; c++) {
            acc[r][c] += bv[c];
            s1[r] = fmaf(acc[r][c], a1v[c], s1[r]);
            s2[r] = fmaf(acc[r][c], a2v[c], s2[r]);
            g_hT[(size_t)(dg * 8 + c) * NN + row] = __float2half(acc[r][c]);
        }
    }
#pragma unroll
    for (int r = 0; r < 4; r++) {
#pragma unroll
        for (int off = 8; off > 0; off >>= 1) {
            s1[r] += __shfl_down_sync(0xffffffffu, s1[r], off, 16);
            s2[r] += __shfl_down_sync(0xffffffffu, s2[r], off, 16);
        }
    }
    if (dg == 0) {
#pragma unroll
        for (int r = 0; r < 4; r++) {
            int row = row0 + rg * 4 + r;
            g_ssrc[row] = s1[r];
            g_sdst[row] = s2[r];
        }
    }
}

// =====================================================================
__global__ void __launch_bounds__(1024) k_prep1()
{
    __shared__ float red[32];
    int tid = threadIdx.x;
    int lane = tid & 31, wid = tid >> 5;
    float vmax = -1e30f;
    for (int j = tid; j < NN; j += 1024) {
        float v = g_sdst[j];
        g_p[j] = expf(v);
        g_q[j] = expf(0.01f * v);
        vmax = fmaxf(vmax, v);
    }
#pragma unroll
    for (int off = 16; off > 0; off >>= 1)
        vmax = fmaxf(vmax, __shfl_down_sync(0xffffffffu, vmax, off));
    if (lane == 0) red[wid] = vmax;
    __syncthreads();
    if (wid == 0) {
        float m = red[lane];
#pragma unroll
        for (int off = 16; off > 0; off >>= 1)
            m = fmaxf(m, __shfl_down_sync(0xffffffffu, m, off));
        if (lane == 0) g_V = m;
    }
}

__global__ void k_prep2(const float* __restrict__ ba)
{
    int i = blockIdx.x * blockDim.x + threadIdx.x;
    if (i >= NN) return;
    float u = g_ssrc[i] + ba[0];
    float t0 = u + g_V;
    float c = fmaxf(t0, 0.01f * t0);
    g_A[i] = expf(u - c);
    g_B[i] = expf(0.01f * u - c);
}

// =====================================================================
// k_main_m: mma.sync (HMMA) mask-weighted GEMM.
// CTA = 512 thr (16 warps, 4m x 4n), 128 i-rows x 128 d over a 2048-j
// segment in 64-j chunks. w tile fp16 + hT tile fp16 in SMEM (stride
// 144B, ldmatrix conflict-free). Denominator via ones-B MMA on wn==0.
// =====================================================================
#define WSTB   144                    // bytes per smem tile row
#define SM_W0  0
#define SM_W1  (128 * WSTB)           // 18432
#define SM_H0  (2 * 128 * WSTB)       // 36864
#define SM_H1  (3 * 128 * WSTB)       // 55296
#define SM_AS  (4 * 128 * WSTB)       // 73728
#define SM_BS  (SM_AS + 512)
#define SM_DYN (SM_BS + 512)          // 74752

__global__ void __launch_bounds__(512) k_main_m(const int* __restrict__ adj)
{
    extern __shared__ char smem[];
    const uint32_t sb = smem_u32(smem);
    float* As = (float*)(smem + SM_AS);
    float* Bs = (float*)(smem + SM_BS);

    const int tid  = threadIdx.x;
    const int wid  = tid >> 5, lane = tid & 31;
    const int rt   = blockIdx.x & 63;
    const int seg  = blockIdx.x >> 6;
    const int row0 = rt * 128;
    const int j0   = seg * SEG;

    // generation mapping: 2 j per thread, 8 rows
    const int jp  = tid & 31;          // j pair index (j = jp*2, jp*2+1)
    const int grp = tid >> 5;          // rows grp*8 .. grp*8+7
    // hT copy mapping: 32B per thread
    const int dd = tid >> 2, qq = tid & 3;
    // warp tile mapping
    const int wm = wid & 3, wn = wid >> 2;

    if (tid < 128) { As[tid] = g_A[row0 + tid]; Bs[tid] = g_B[row0 + tid]; }

    float acc[2][4][4];
#pragma unroll
    for (int mt = 0; mt < 2; mt++)
#pragma unroll
        for (int nt = 0; nt < 4; nt++)
#pragma unroll
            for (int k = 0; k < 4; k++) acc[mt][nt][k] = 0.f;
    float dacc[2][4] = {{0.f,0.f,0.f,0.f},{0.f,0.f,0.f,0.f}};
    const uint32_t ones = 0x3C003C00u;

    // ---- prologue: stage h[0], prefetch adj[0], p/q[0] ----
    int2 adjv[8];
    float2 p2, q2;
    {
        const __half* hs = g_hT + (size_t)dd * NN + j0 + qq * 16;
        uint32_t hd = sb + SM_H0 + dd * WSTB + qq * 32;
        CPASYNC16(hd, hs);
        CPASYNC16(hd + 16, hs + 8);
        CPCOMMIT();
        const int* ap = adj + (size_t)(row0 + grp * 8) * NN + j0 + jp * 2;
#pragma unroll
        for (int k = 0; k < 8; k++) adjv[k] = *(const int2*)(ap + (size_t)k * NN);
        p2 = *(const float2*)&g_p[j0 + jp * 2];
        q2 = *(const float2*)&g_q[j0 + jp * 2];
    }
    __syncthreads();   // As/Bs visible

    for (int c = 0; c < NCH; c++) {
        const int b = c & 1;
        const uint32_t wb = sb + (b ? SM_W1 : SM_W0);
        const uint32_t hb = sb + (b ? SM_H1 : SM_H0);

        // ---- generate w tile from prefetched regs ----
#pragma unroll
        for (int k = 0; k < 8; k++) {
            const int i = grp * 8 + k;
            const float Ai = As[i], Bi = Bs[i];
            float w0 = adjv[k].x ? fmaxf(Ai * p2.x, Bi * q2.x) : 0.f;
            float w1 = adjv[k].y ? fmaxf(Ai * p2.y, Bi * q2.y) : 0.f;
            __half2 h2 = __floats2half2_rn(w0, w1);
            *(uint32_t*)(smem + (b ? SM_W1 : SM_W0) + i * WSTB + jp * 4) =
                *(uint32_t*)&h2;
        }
        CPWAIT0();          // h[c] arrived
        __syncthreads();    // tiles visible to all warps

        // ---- prefetch chunk c+1 ----
        if (c + 1 < NCH) {
            const int jb1 = j0 + (c + 1) * KC;
            const __half* hs = g_hT + (size_t)dd * NN + jb1 + qq * 16;
            uint32_t hd = sb + (b ? SM_H0 : SM_H1) + dd * WSTB + qq * 32;
            CPASYNC16(hd, hs);
            CPASYNC16(hd + 16, hs + 8);
            CPCOMMIT();
            const int* ap = adj + (size_t)(row0 + grp * 8) * NN + jb1 + jp * 2;
#pragma unroll
            for (int k = 0; k < 8; k++) adjv[k] = *(const int2*)(ap + (size_t)k * NN);
            p2 = *(const float2*)&g_p[jb1 + jp * 2];
            q2 = *(const float2*)&g_q[jb1 + jp * 2];
        }

        // ---- MMA over the chunk: 4 k-steps ----
        const int mi = lane >> 3, r8 = lane & 7;
#pragma unroll
        for (int ks = 0; ks < 4; ks++) {
            uint32_t a[2][4];
#pragma unroll
            for (int mt = 0; mt < 2; mt++) {
                int arow = wm * 32 + mt * 16 + ((mi & 1) ? 8 : 0) + r8;
                int acol = ks * 16 + ((mi >> 1) ? 8 : 0);
                LDMX4(a[mt][0], a[mt][1], a[mt][2], a[mt][3],
                      wb + arow * WSTB + acol * 2);
            }
            uint32_t bfr[4][2];
            {
                int nrow = wn * 32 + (mi >> 1) * 8 + r8;
                int bcol = ks * 16 + ((mi & 1) ? 8 : 0);
                LDMX4(bfr[0][0], bfr[0][1], bfr[1][0], bfr[1][1],
                      hb + nrow * WSTB + bcol * 2);
                LDMX4(bfr[2][0], bfr[2][1], bfr[3][0], bfr[3][1],
                      hb + (nrow + 16) * WSTB + bcol * 2);
            }
#pragma unroll
            for (int mt = 0; mt < 2; mt++)
#pragma unroll
                for (int nt = 0; nt < 4; nt++)
                    MMA16816(acc[mt][nt], a[mt][0], a[mt][1], a[mt][2], a[mt][3],
                             bfr[nt][0], bfr[nt][1]);
            if (wn == 0) {
#pragma unroll
                for (int mt = 0; mt < 2; mt++)
                    MMA16816(dacc[mt], a[mt][0], a[mt][1], a[mt][2], a[mt][3],
                             ones, ones);
            }
        }
    }

    // ---- epilogue ----
    const int rlo = row0 + wm * 32 + (lane >> 2);
    const int col = wn * 32 + (lane & 3) * 2;
    float* pp = g_part + (size_t)seg * NN * DOUT;
#pragma unroll
    for (int mt = 0; mt < 2; mt++) {
#pragma unroll
        for (int nt = 0; nt < 4; nt++) {
            float2 lo = make_float2(acc[mt][nt][0], acc[mt][nt][1]);
            float2 hi = make_float2(acc[mt][nt][2], acc[mt][nt][3]);
            *(float2*)&pp[(size_t)(rlo + mt * 16) * DOUT + nt * 8 + col] = lo;
            *(float2*)&pp[(size_t)(rlo + mt * 16 + 8) * DOUT + nt * 8 + col] = hi;
        }
    }
    if (wn == 0 && (lane & 3) == 0) {
#pragma unroll
        for (int mt = 0; mt < 2; mt++) {
            g_denomp[seg * NN + rlo + mt * 16]     = dacc[mt][0];
            g_denomp[seg * NN + rlo + mt * 16 + 8] = dacc[mt][2];
        }
    }
}

// =====================================================================
__global__ void __launch_bounds__(256) k_combine(float* __restrict__ out)
{
    const int idx = blockIdx.x * 256 + threadIdx.x;
    const int i  = idx >> 5;
    const int dq = idx & 31;
    float4 s = make_float4(0.f, 0.f, 0.f, 0.f);
    float den = 0.f;
#pragma unroll
    for (int sg = 0; sg < JS; sg++) {
        float4 v = *(const float4*)&g_part[((size_t)sg * NN + i) * DOUT + dq * 4];
        s.x += v.x; s.y += v.y; s.z += v.z; s.w += v.w;
        den += g_denomp[sg * NN + i];
    }
    const float inv = 1.0f / fmaxf(den, 1e-30f);
    s.x *= inv; s.y *= inv; s.z *= inv; s.w *= inv;
    *(float4*)&out[(size_t)i * DOUT + dq * 4] = s;
}

// =====================================================================
extern "C" void kernel_launch(void* const* d_in, const int* in_sizes, int n_in,
                              void* d_out, int out_size)
{
    const float* x   = (const float*)d_in[0];
    const int*   adj = (const int*)  d_in[1];
    const float* W   = (const float*)d_in[2];
    const float* bW  = (const float*)d_in[3];
    const float* a1  = (const float*)d_in[4];
    const float* a2  = (const float*)d_in[5];
    const float* ba  = (const float*)d_in[6];
    float* out = (float*)d_out;

    cudaFuncSetAttribute(k_main_m, cudaFuncAttributeMaxDynamicSharedMemorySize, SM_DYN);

    k_linear<<<NN / TI, 128>>>(x, W, bW, a1, a2);
    k_prep1<<<1, 1024>>>();
    k_prep2<<<NN / 256, 256>>>(ba);
    k_main_m<<<64 * JS, 512, SM_DYN>>>(adj);
    k_combine<<<NN * 32 / 256, 256>>>(out);
}

// round 5
// speedup vs baseline: 4.7650x; 1.0814x over previous
#include <cuda_runtime.h>
#include <cuda_fp16.h>
#include <math.h>
#include <stdint.h>

#define NN   8192
#define DIN  256
#define DOUT 128
#define TI   32
#define JS   4              // j segments
#define SEG  (NN / JS)      // 2048
#define KC   64             // j per chunk
#define NCH  (SEG / KC)     // 32
#define RT   64             // i-rows per CTA tile

// ---- scratch ----
__device__ float  g_ssrc[NN];
__device__ float  g_sdst[NN];
__device__ __half g_ph[NN];
__device__ __half g_qh[NN];
__device__ __half g_Ah[NN];
__device__ __half g_Bh[NN];
__device__ float  g_V;
__device__ __half g_hT[(size_t)DOUT * NN];            // h transposed, fp16 (2MB)
__device__ float  g_part[(size_t)JS * NN * DOUT];     // 16MB partial numerators
__device__ float  g_denomp[JS * NN];

// ============================ PTX helpers ============================
__device__ __forceinline__ uint32_t smem_u32(const void* p) {
    uint32_t a;
    asm("{ .reg .u64 t; cvta.to.shared.u64 t, %1; cvt.u32.u64 %0, t; }" : "=r"(a) : "l"(p));
    return a;
}
#define LDMX4(r0, r1, r2, r3, a) \
    asm volatile("ldmatrix.sync.aligned.m8n8.x4.shared.b16 {%0,%1,%2,%3}, [%4];" \
                 : "=r"(r0), "=r"(r1), "=r"(r2), "=r"(r3) : "r"(a))
#define MMA16816(c, a0, a1, a2, a3, b0, b1) \
    asm volatile("mma.sync.aligned.m16n8k16.row.col.f32.f16.f16.f32 " \
                 "{%0,%1,%2,%3},{%4,%5,%6,%7},{%8,%9},{%0,%1,%2,%3};" \
                 : "+f"((c)[0]), "+f"((c)[1]), "+f"((c)[2]), "+f"((c)[3]) \
                 : "r"(a0), "r"(a1), "r"(a2), "r"(a3), "r"(b0), "r"(b1))
#define CPASYNC16(dst, src) \
    asm volatile("cp.async.ca.shared.global [%0], [%1], 16;" :: "r"(dst), "l"(src))
#define CPCOMMIT() asm volatile("cp.async.commit_group;" ::: "memory")
#define CPWAIT0()  asm volatile("cp.async.wait_group 0;" ::: "memory")

// =====================================================================
// k1: h = x@W + bW (fp32); hT fp16 coalesced; s_src = h.a1, s_dst = h.a2
// =====================================================================
__global__ void __launch_bounds__(128) k_linear(
    const float* __restrict__ x, const float* __restrict__ W,
    const float* __restrict__ bW, const float* __restrict__ a1,
    const float* __restrict__ a2)
{
    __shared__ __align__(16) float xs[16][33];
    __shared__ __align__(16) float Ws[16][DOUT];

    const int tid = threadIdx.x;
    const int dg = tid & 15;
    const int rg = tid >> 4;
    const int row0 = blockIdx.x * TI;

    float acc[4][8];
#pragma unroll
    for (int r = 0; r < 4; r++)
#pragma unroll
        for (int c = 0; c < 8; c++) acc[r][c] = 0.f;

    for (int kb = 0; kb < DIN; kb += 16) {
        __syncthreads();
#pragma unroll
        for (int m = 0; m < 4; m++) {
            int i = tid + 128 * m;
            int rr = i >> 4, kk = i & 15;
            xs[kk][rr] = x[(row0 + rr) * DIN + kb + kk];
        }
        const float4* Wg = (const float4*)(W + kb * DOUT);
        float4* Wl = (float4*)Ws;
#pragma unroll
        for (int m = 0; m < 4; m++) Wl[tid + 128 * m] = Wg[tid + 128 * m];
        __syncthreads();

#pragma unroll
        for (int k = 0; k < 16; k++) {
            float a_[4];
#pragma unroll
            for (int r = 0; r < 4; r++) a_[r] = xs[k][rg * 4 + r];
            float4 b0 = *(const float4*)&Ws[k][dg * 8];
            float4 b1 = *(const float4*)&Ws[k][dg * 8 + 4];
            float b_[8] = {b0.x, b0.y, b0.z, b0.w, b1.x, b1.y, b1.z, b1.w};
#pragma unroll
            for (int r = 0; r < 4; r++)
#pragma unroll
                for (int c = 0; c < 8; c++) acc[r][c] = fmaf(a_[r], b_[c], acc[r][c]);
        }
    }

    float4 bv0 = *(const float4*)&bW[dg * 8];
    float4 bv1 = *(const float4*)&bW[dg * 8 + 4];
    float bv[8] = {bv0.x, bv0.y, bv0.z, bv0.w, bv1.x, bv1.y, bv1.z, bv1.w};
    float4 a10 = *(const float4*)&a1[dg * 8];
    float4 a11 = *(const float4*)&a1[dg * 8 + 4];
    float a1v[8] = {a10.x, a10.y, a10.z, a10.w, a11.x, a11.y, a11.z, a11.w};
    float4 a20 = *(const float4*)&a2[dg * 8];
    float4 a21 = *(const float4*)&a2[dg * 8 + 4];
    float a2v[8] = {a20.x, a20.y, a20.z, a20.w, a21.x, a21.y, a21.z, a21.w};

    float s1[4], s2[4];
#pragma unroll
    for (int r = 0; r < 4; r++) {
        s1[r] = 0.f; s2[r] = 0.f;
#pragma unroll
        for (int c = 0; c < 8; c++) {
            acc[r][c] += bv[c];
            s1[r] = fmaf(acc[r][c], a1v[c], s1[r]);
            s2[r] = fmaf(acc[r][c], a2v[c], s2[r]);
        }
    }
    // hT store: per (thread, c): 4 consecutive rows -> one 8B store
#pragma unroll
    for (int c = 0; c < 8; c++) {
        __half2 lo = __floats2half2_rn(acc[0][c], acc[1][c]);
        __half2 hi = __floats2half2_rn(acc[2][c], acc[3][c]);
        uint2 pk = make_uint2(*(uint32_t*)&lo, *(uint32_t*)&hi);
        *(uint2*)(g_hT + (size_t)(dg * 8 + c) * NN + row0 + rg * 4) = pk;
    }
#pragma unroll
    for (int r = 0; r < 4; r++) {
#pragma unroll
        for (int off = 8; off > 0; off >>= 1) {
            s1[r] += __shfl_down_sync(0xffffffffu, s1[r], off, 16);
            s2[r] += __shfl_down_sync(0xffffffffu, s2[r], off, 16);
        }
    }
    if (dg == 0) {
#pragma unroll
        for (int r = 0; r < 4; r++) {
            int row = row0 + rg * 4 + r;
            g_ssrc[row] = s1[r];
            g_sdst[row] = s2[r];
        }
    }
}

// =====================================================================
__global__ void __launch_bounds__(1024) k_vmax()
{
    __shared__ float red[32];
    int tid = threadIdx.x;
    int lane = tid & 31, wid = tid >> 5;
    float vmax = -1e30f;
    for (int j = tid; j < NN; j += 1024) vmax = fmaxf(vmax, g_sdst[j]);
#pragma unroll
    for (int off = 16; off > 0; off >>= 1)
        vmax = fmaxf(vmax, __shfl_down_sync(0xffffffffu, vmax, off));
    if (lane == 0) red[wid] = vmax;
    __syncthreads();
    if (wid == 0) {
        float m = red[lane];
#pragma unroll
        for (int off = 16; off > 0; off >>= 1)
            m = fmaxf(m, __shfl_down_sync(0xffffffffu, m, off));
        if (lane == 0) g_V = m;
    }
}

// A' = exp(u+V-c) <= 1, B' = exp(.01(u+V)-c) <= 1, c = lrelu(u+V)
// p' = exp(v-V) <= 1, q' = exp(.01(v-V)) <= 1
__global__ void k_prep(const float* __restrict__ ba)
{
    int i = blockIdx.x * blockDim.x + threadIdx.x;
    if (i >= NN) return;
    const float V = g_V;
    float u = g_ssrc[i] + ba[0];
    float t = u + V;
    float c = fmaxf(t, 0.01f * t);
    g_Ah[i] = __float2half(expf(t - c));
    g_Bh[i] = __float2half(expf(0.01f * t - c));
    float v = g_sdst[i] - V;
    g_ph[i] = __float2half(expf(v));
    g_qh[i] = __float2half(expf(0.01f * v));
}

// =====================================================================
// k_main_m: HMMA mask-weighted GEMM. CTA = 256 thr (8 warps, 2m x 4n),
// 64 i-rows x 128 d over a 2048-j segment in 64-j chunks.
// =====================================================================
#define WSTB   144
#define SM_W0  0
#define SM_W1  (RT * WSTB)              // 9216
#define SM_H0  (2 * RT * WSTB)          // 18432
#define SM_H1  (SM_H0 + 128 * WSTB)     // 36864
#define SM_AS  (SM_H1 + 128 * WSTB)     // 55296
#define SM_BS  (SM_AS + 128)
#define SM_DYN (SM_BS + 128 + 256)

__global__ void __launch_bounds__(256, 3) k_main_m(const int* __restrict__ adj)
{
    extern __shared__ char smem[];
    const uint32_t sb = smem_u32(smem);
    __half* As = (__half*)(smem + SM_AS);
    __half* Bs = (__half*)(smem + SM_BS);

    const int tid  = threadIdx.x;
    const int wid  = tid >> 5, lane = tid & 31;
    const int rt   = blockIdx.x & 127;
    const int seg  = blockIdx.x >> 7;
    const int row0 = rt * RT;
    const int j0   = seg * SEG;

    const int jp  = tid & 31;          // j pair (j = jp*2, jp*2+1)
    const int grp = tid >> 5;          // rows grp*8 .. grp*8+7
    const int dd  = tid >> 1, qq = tid & 1;   // hT copy: 64B per thread
    const int wm  = wid & 1, wn = wid >> 1;

    if (tid < RT) { As[tid] = g_Ah[row0 + tid]; Bs[tid] = g_Bh[row0 + tid]; }

    float acc[2][4][4];
#pragma unroll
    for (int mt = 0; mt < 2; mt++)
#pragma unroll
        for (int nt = 0; nt < 4; nt++)
#pragma unroll
            for (int k = 0; k < 4; k++) acc[mt][nt][k] = 0.f;
    float dacc[2][4] = {{0.f,0.f,0.f,0.f},{0.f,0.f,0.f,0.f}};
    const uint32_t ones = 0x3C003C00u;

    // ---- prologue: stage h[0], prefetch adj[0], p/q[0] ----
    int2 adjv[8];
    uint32_t p2r, q2r;
    {
        const __half* hs = g_hT + (size_t)dd * NN + j0 + qq * 32;
        uint32_t hd = sb + SM_H0 + dd * WSTB + qq * 64;
#pragma unroll
        for (int k = 0; k < 4; k++) CPASYNC16(hd + 16 * k, hs + 8 * k);
        CPCOMMIT();
        const int* ap = adj + (size_t)(row0 + grp * 8) * NN + j0 + jp * 2;
#pragma unroll
        for (int k = 0; k < 8; k++) adjv[k] = *(const int2*)(ap + (size_t)k * NN);
        p2r = *(const uint32_t*)&g_ph[j0 + jp * 2];
        q2r = *(const uint32_t*)&g_qh[j0 + jp * 2];
    }
    __syncthreads();   // As/Bs visible

    for (int c = 0; c < NCH; c++) {
        const int b = c & 1;
        const uint32_t wb = sb + (b ? SM_W1 : SM_W0);
        const uint32_t hb = sb + (b ? SM_H1 : SM_H0);

        // ---- generate w tile (half2 + mask-multiply) ----
        {
            const __half2 p2 = *(__half2*)&p2r;
            const __half2 q2 = *(__half2*)&q2r;
#pragma unroll
            for (int k = 0; k < 8; k++) {
                const int i = grp * 8 + k;
                __half2 A2 = __half2half2(As[i]);
                __half2 B2 = __half2half2(Bs[i]);
                uint32_t m = (uint32_t)(adjv[k].x | (adjv[k].y << 16)) * 0xFFFFu;
                __half2 w = __hmax2(__hmul2(A2, p2), __hmul2(B2, q2));
                *(uint32_t*)(smem + (b ? SM_W1 : SM_W0) + i * WSTB + jp * 4) =
                    (*(uint32_t*)&w) & m;
            }
        }
        CPWAIT0();
        __syncthreads();

        // ---- prefetch chunk c+1 ----
        if (c + 1 < NCH) {
            const int jb1 = j0 + (c + 1) * KC;
            const __half* hs = g_hT + (size_t)dd * NN + jb1 + qq * 32;
            uint32_t hd = sb + (b ? SM_H0 : SM_H1) + dd * WSTB + qq * 64;
#pragma unroll
            for (int k = 0; k < 4; k++) CPASYNC16(hd + 16 * k, hs + 8 * k);
            CPCOMMIT();
            const int* ap = adj + (size_t)(row0 + grp * 8) * NN + jb1 + jp * 2;
#pragma unroll
            for (int k = 0; k < 8; k++) adjv[k] = *(const int2*)(ap + (size_t)k * NN);
            p2r = *(const uint32_t*)&g_ph[jb1 + jp * 2];
            q2r = *(const uint32_t*)&g_qh[jb1 + jp * 2];
        }

        // ---- MMA: 4 k-steps ----
        const int mi = lane >> 3, r8 = lane & 7;
#pragma unroll
        for (int ks = 0; ks < 4; ks++) {
            uint32_t a[2][4];
#pragma unroll
            for (int mt = 0; mt < 2; mt++) {
                int arow = wm * 32 + mt * 16 + ((mi & 1) ? 8 : 0) + r8;
                int acol = ks * 16 + ((mi >> 1) ? 8 : 0);
                LDMX4(a[mt][0], a[mt][1], a[mt][2], a[mt][3],
                      wb + arow * WSTB + acol * 2);
            }
            uint32_t bfr[4][2];
            {
                int nrow = wn * 32 + (mi >> 1) * 8 + r8;
                int bcol = ks * 16 + ((mi & 1) ? 8 : 0);
                LDMX4(bfr[0][0], bfr[0][1], bfr[1][0], bfr[1][1],
                      hb + nrow * WSTB + bcol * 2);
                LDMX4(bfr[2][0], bfr[2][1], bfr[3][0], bfr[3][1],
                      hb + (nrow + 16) * WSTB + bcol * 2);
            }
#pragma unroll
            for (int mt = 0; mt < 2; mt++)
#pragma unroll
                for (int nt = 0; nt < 4; nt++)
                    MMA16816(acc[mt][nt], a[mt][0], a[mt][1], a[mt][2], a[mt][3],
                             bfr[nt][0], bfr[nt][1]);
            if (wn == 0) {
#pragma unroll
                for (int mt = 0; mt < 2; mt++)
                    MMA16816(dacc[mt], a[mt][0], a[mt][1], a[mt][2], a[mt][3],
                             ones, ones);
            }
        }
    }

    // ---- epilogue ----
    const int rlo = row0 + wm * 32 + (lane >> 2);
    const int col = wn * 32 + (lane & 3) * 2;
    float* pp = g_part + (size_t)seg * NN * DOUT;
#pragma unroll
    for (int mt = 0; mt < 2; mt++) {
#pragma unroll
        for (int nt = 0; nt < 4; nt++) {
            float2 lo = make_float2(acc[mt][nt][0], acc[mt][nt][1]);
            float2 hi = make_float2(acc[mt][nt][2], acc[mt][nt][3]);
            *(float2*)&pp[(size_t)(rlo + mt * 16) * DOUT + nt * 8 + col] = lo;
            *(float2*)&pp[(size_t)(rlo + mt * 16 + 8) * DOUT + nt * 8 + col] = hi;
        }
    }
    if (wn == 0 && (lane & 3) == 0) {
#pragma unroll
        for (int mt = 0; mt < 2; mt++) {
            g_denomp[seg * NN + rlo + mt * 16]     = dacc[mt][0];
            g_denomp[seg * NN + rlo + mt * 16 + 8] = dacc[mt][2];
        }
    }
}

// =====================================================================
__global__ void __launch_bounds__(256) k_combine(float* __restrict__ out)
{
    const int idx = blockIdx.x * 256 + threadIdx.x;
    const int i  = idx >> 5;
    const int dq = idx & 31;
    float4 s = make_float4(0.f, 0.f, 0.f, 0.f);
    float den = 0.f;
#pragma unroll
    for (int sg = 0; sg < JS; sg++) {
        float4 v = *(const float4*)&g_part[((size_t)sg * NN + i) * DOUT + dq * 4];
        s.x += v.x; s.y += v.y; s.z += v.z; s.w += v.w;
        den += g_denomp[sg * NN + i];
    }
    const float inv = 1.0f / fmaxf(den, 1e-30f);
    s.x *= inv; s.y *= inv; s.z *= inv; s.w *= inv;
    *(float4*)&out[(size_t)i * DOUT + dq * 4] = s;
}

// =====================================================================
extern "C" void kernel_launch(void* const* d_in, const int* in_sizes, int n_in,
                              void* d_out, int out_size)
{
    const float* x   = (const float*)d_in[0];
    const int*   adj = (const int*)  d_in[1];
    const float* W   = (const float*)d_in[2];
    const float* bW  = (const float*)d_in[3];
    const float* a1  = (const float*)d_in[4];
    const float* a2  = (const float*)d_in[5];
    const float* ba  = (const float*)d_in[6];
    float* out = (float*)d_out;

    cudaFuncSetAttribute(k_main_m, cudaFuncAttributeMaxDynamicSharedMemorySize, SM_DYN);

    k_linear<<<NN / TI, 128>>>(x, W, bW, a1, a2);
    k_vmax<<<1, 1024>>>();
    k_prep<<<NN / 256, 256>>>(ba);
    k_main_m<<<128 * JS, 256, SM_DYN>>>(adj);
    k_combine<<<NN * 32 / 256, 256>>>(out);
}